// round 15
// baseline (speedup 1.0000x reference)
#include <cuda_runtime.h>
#include <math.h>

#define NB 64
#define V 256
#define F 64
#define C 64
#define ALPHA_C 0.1f
#define YSZ (NB * V * F)

typedef unsigned long long ull;

// ---------------- packed f32x2 helpers (mega1 y-path) ----------------
__device__ __forceinline__ ull pk2(float v) {
    ull r;
    asm("mov.b64 %0, {%1, %1};" : "=l"(r) : "f"(v));
    return r;
}
__device__ __forceinline__ ull fma2(ull a, ull b, ull c) {
    ull r;
    asm("fma.rn.f32x2 %0, %1, %2, %3;" : "=l"(r) : "l"(a), "l"(b), "l"(c));
    return r;
}
__device__ __forceinline__ void upk2(ull v, float& lo, float& hi) {
    asm("mov.b64 {%0, %1}, %2;" : "=f"(lo), "=f"(hi) : "l"(v));
}

// ---------------- tf32 mma helpers ----------------
__device__ __forceinline__ unsigned cvt_tf32(float f) {
    unsigned r;
    asm("cvt.rna.tf32.f32 %0, %1;" : "=r"(r) : "f"(f));
    return r;
}
__device__ __forceinline__ void mma_tf32(float* c,
    unsigned a0, unsigned a1, unsigned a2, unsigned a3,
    unsigned b0, unsigned b1) {
    asm("mma.sync.aligned.m16n8k8.row.col.f32.tf32.tf32.f32 "
        "{%0,%1,%2,%3}, {%4,%5,%6,%7}, {%8,%9}, {%0,%1,%2,%3};"
        : "+f"(c[0]), "+f"(c[1]), "+f"(c[2]), "+f"(c[3])
        : "r"(a0), "r"(a1), "r"(a2), "r"(a3), "r"(b0), "r"(b1));
}

// ---------------- scratch (no allocations allowed) ----------------
__device__ float g_pc[NB * 4 * V];
__device__ float g_pA[NB * 4 * V];
__device__ float g_pB[NB * 4 * V];
__device__ float g_lossP[NB];
__device__ float g_Y[3 * YSZ];   // Y0 = x@(th0-th2), Y1 = x@(-th1), Y2 = x@(2*th2)
__device__ int g_cntG;           // global arrival counter (zero-init; self-resetting)

__constant__ int c_IT[10] = {0, 0, 0, 0, 1, 1, 1, 2, 2, 3};
__constant__ int c_JT[10] = {0, 1, 2, 3, 1, 2, 3, 2, 3, 3};

#define N_PW 640
#define N_YG 768
#define POOL_F 10880
// overlay map (floats): xi 0..4352 | xj 4352..8704 | a_s 8704 | NI 8768 | NJ 8832
// NPI 8896..9152 | NPJ 9152..9408 | d2t overlays xj (4352) after MMA |
// stats partials P_* overlay 4352..10880 after dd is register-cached
#define A_S 8704
#define NI_O 8768
#define NJ_O 8832
#define NPI_O 8896
#define NPJ_O 9152
#define P_CC 4352
#define P_AC (4352 + 1088)
#define P_BC (4352 + 2176)
#define P_CR (4352 + 3264)
#define P_AR (4352 + 4352)
#define P_BR (4352 + 5440)

// ---------------- mega kernel 1: pairwise (idx<640) + y_gemm (idx>=640) ----------------
__global__ __launch_bounds__(256) void mega1_kernel(
    const float* __restrict__ x, const float* __restrict__ a,
    const float* __restrict__ theta, float* __restrict__ s_out) {
    __shared__ __align__(16) float pool[POOL_F];

    const int t = threadIdx.x;
    const int tx = t & 15, ty = t >> 4;

    if (blockIdx.x >= N_PW) {
        // ================= y_gemm part =================
        int idx = blockIdx.x - N_PW;
        const int it = idx & 3;
        const int m = (idx >> 2) % 3;
        const int b = idx / 12;
        const int i0 = it * 64;
        float (*sW)[64] = (float(*)[64])pool;
        float (*sX)[68] = (float(*)[68])(pool + 4096);
        const float* xb = x + b * V * F;

        for (int q = t; q < 64 * 16; q += 256) {
            int f = q >> 4;
            int c4 = (q & 15) * 4;
            float4 v;
            if (m == 0) {
                float4 t0 = *(const float4*)&theta[(0 * F + f) * C + c4];
                float4 t2 = *(const float4*)&theta[(2 * F + f) * C + c4];
                v = make_float4(t0.x - t2.x, t0.y - t2.y, t0.z - t2.z, t0.w - t2.w);
            } else if (m == 1) {
                float4 t1 = *(const float4*)&theta[(1 * F + f) * C + c4];
                v = make_float4(-t1.x, -t1.y, -t1.z, -t1.w);
            } else {
                float4 t2 = *(const float4*)&theta[(2 * F + f) * C + c4];
                v = make_float4(2.f * t2.x, 2.f * t2.y, 2.f * t2.z, 2.f * t2.w);
            }
            *(float4*)&sW[f][c4] = v;
        }
        for (int q = t; q < 64 * 16; q += 256) {
            int i = q >> 4;
            int f4 = (q & 15) * 4;
            float4 v = *(const float4*)&xb[(i0 + i) * F + f4];
            sX[f4 + 0][i] = v.x;
            sX[f4 + 1][i] = v.y;
            sX[f4 + 2][i] = v.z;
            sX[f4 + 3][i] = v.w;
        }
        __syncthreads();

        ull acc2[4][2];
#pragma unroll
        for (int ii = 0; ii < 4; ii++)
#pragma unroll
            for (int p = 0; p < 2; p++) acc2[ii][p] = 0ULL;

#pragma unroll 4
        for (int k = 0; k < 64; k++) {
            float4 xa = *(const float4*)&sX[k][ty * 4];
            ulonglong2 wp = *(const ulonglong2*)&sW[k][tx * 4];
            float xv[4] = {xa.x, xa.y, xa.z, xa.w};
#pragma unroll
            for (int ii = 0; ii < 4; ii++) {
                ull xv2 = pk2(xv[ii]);
                acc2[ii][0] = fma2(xv2, wp.x, acc2[ii][0]);
                acc2[ii][1] = fma2(xv2, wp.y, acc2[ii][1]);
            }
        }

        float* y = g_Y + m * YSZ + b * V * F;
#pragma unroll
        for (int ii = 0; ii < 4; ii++) {
            int row = i0 + ty * 4 + ii;
            float4 o;
            upk2(acc2[ii][0], o.x, o.y);
            upk2(acc2[ii][1], o.z, o.w);
            *(float4*)&y[row * F + tx * 4] = o;
        }
        return;
    }

    // ================= pairwise part =================
    const int b = blockIdx.x / 10;
    const int tile = blockIdx.x % 10;
    const int it = c_IT[tile], jt = c_JT[tile];
    const int i0 = it * 64, j0 = jt * 64;
    const bool offdiag = (it != jt);
    const float* xb = x + b * V * F;

    float (*xi_t)[68] = (float(*)[68])pool;           // [f][i]
    float (*xj_t)[68] = (float(*)[68])(pool + 4352);  // [f][j] (plain, not negated)
    float* a_s = pool + A_S;

    for (int e = t; e < 64 * F; e += 256) {
        int row = e >> 6;
        int f = e & 63;
        xi_t[f][row] = xb[(i0 + row) * F + f];
        xj_t[f][row] = xb[(j0 + row) * F + f];
    }
    if (t < F) a_s[t] = a[t];
    __syncthreads();

    // ---- 1. score-only scalar loop (FADD + FFMA-with-|.|, no d^2 chain) ----
    float sc[4][4];
#pragma unroll
    for (int ii = 0; ii < 4; ii++)
#pragma unroll
        for (int jj = 0; jj < 4; jj++) sc[ii][jj] = 0.f;

#pragma unroll 4
    for (int f = 0; f < F; f++) {
        float4 xi4 = *(const float4*)&xi_t[f][ty * 4];
        float4 xj4 = *(const float4*)&xj_t[f][tx * 4];
        float xiv[4] = {xi4.x, xi4.y, xi4.z, xi4.w};
        float xjv[4] = {xj4.x, xj4.y, xj4.z, xj4.w};
        float af = a_s[f];
#pragma unroll
        for (int ii = 0; ii < 4; ii++)
#pragma unroll
            for (int jj = 0; jj < 4; jj++) {
                float d = xiv[ii] - xjv[jj];
                sc[ii][jj] = fmaf(fabsf(d), af, sc[ii][jj]);
            }
    }

    // ---- 2. row/col squared norms (partials) ----
    {
        int row = t & 63, qtr = t >> 6;
        float npi = 0.f, npj = 0.f;
#pragma unroll
        for (int u = 0; u < 16; u++) {
            float vi = xi_t[qtr * 16 + u][row];
            float vj = xj_t[qtr * 16 + u][row];
            npi = fmaf(vi, vi, npi);
            npj = fmaf(vj, vj, npj);
        }
        pool[NPI_O + qtr * 64 + row] = npi;
        pool[NPJ_O + qtr * 64 + row] = npj;
    }

    // ---- 3. Gram tile via tf32 mma: gacc = Xi @ Xj^T (raw fp32 bits, HW truncates) ----
    const int w = t >> 5, l = t & 31;
    const int g2 = l >> 2, q4 = l & 3;
    const int wr = (w & 3) * 16;     // warp row base
    const int nc = (w >> 2) * 32;    // warp col base

    float gacc[4][4];
#pragma unroll
    for (int nt = 0; nt < 4; nt++)
#pragma unroll
        for (int u = 0; u < 4; u++) gacc[nt][u] = 0.f;

#pragma unroll
    for (int kk = 0; kk < 8; kk++) {
        int kc = kk * 8;
        unsigned a0 = __float_as_uint(xi_t[kc + q4][wr + g2]);
        unsigned a1 = __float_as_uint(xi_t[kc + q4][wr + g2 + 8]);
        unsigned a2 = __float_as_uint(xi_t[kc + 4 + q4][wr + g2]);
        unsigned a3 = __float_as_uint(xi_t[kc + 4 + q4][wr + g2 + 8]);
#pragma unroll
        for (int nt = 0; nt < 4; nt++) {
            int ncol = nc + nt * 8 + g2;
            unsigned b0 = __float_as_uint(xj_t[kc + q4][ncol]);
            unsigned b1 = __float_as_uint(xj_t[kc + 4 + q4][ncol]);
            mma_tf32(gacc[nt], a0, a1, a2, a3, b0, b1);
        }
    }
    __syncthreads();  // NP partials written; xi/xj reads complete

    // ---- 4. reduce norms ----
    if (t < 64) {
        pool[NI_O + t] = pool[NPI_O + t] + pool[NPI_O + 64 + t] +
                         pool[NPI_O + 128 + t] + pool[NPI_O + 192 + t];
        pool[NJ_O + t] = pool[NPJ_O + t] + pool[NPJ_O + 64 + t] +
                         pool[NPJ_O + 128 + t] + pool[NPJ_O + 192 + t];
    }
    __syncthreads();

    // ---- 5. d2 tile = ni + nj - 2G (overlays dead xj region); exact 0 on diagonal ----
    float (*d2t)[68] = (float(*)[68])(pool + 4352);
#pragma unroll
    for (int nt = 0; nt < 4; nt++) {
        int col = nc + nt * 8 + 2 * q4;
        int r0 = wr + g2, r1 = r0 + 8;
        float ni0 = pool[NI_O + r0], ni1 = pool[NI_O + r1];
        float nj0 = pool[NJ_O + col], nj1 = pool[NJ_O + col + 1];
        float v00 = ni0 + nj0 - 2.f * gacc[nt][0];
        float v01 = ni0 + nj1 - 2.f * gacc[nt][1];
        float v10 = ni1 + nj0 - 2.f * gacc[nt][2];
        float v11 = ni1 + nj1 - 2.f * gacc[nt][3];
        if (!offdiag) {
            if (r0 == col) v00 = 0.f;
            if (r0 == col + 1) v01 = 0.f;
            if (r1 == col) v10 = 0.f;
            if (r1 == col + 1) v11 = 0.f;
        }
        *(float2*)&d2t[r0][col] = make_float2(v00, v01);
        *(float2*)&d2t[r1][col] = make_float2(v10, v11);
    }
    __syncthreads();

    // ---- 6. cache dd in registers (then d2t region becomes free for partials) ----
    float dd[4][4];
#pragma unroll
    for (int ii = 0; ii < 4; ii++)
        *(float4*)dd[ii] = *(const float4*)&d2t[ty * 4 + ii][tx * 4];
    __syncthreads();

    // ---- 7. stats epilogue (unchanged math) ----
    float tm[4][4];
    float cpart[4] = {0.f, 0.f, 0.f, 0.f};
    float Apart[4] = {0.f, 0.f, 0.f, 0.f};
    float Bpart[4] = {0.f, 0.f, 0.f, 0.f};
    float rc[4] = {0.f, 0.f, 0.f, 0.f};
    float rA[4] = {0.f, 0.f, 0.f, 0.f};
    float rB[4] = {0.f, 0.f, 0.f, 0.f};

#pragma unroll
    for (int ii = 0; ii < 4; ii++) {
#pragma unroll
        for (int jj = 0; jj < 4; jj++) {
            float tmp = __expf(-fmaxf(sc[ii][jj], 0.f));
            tm[ii][jj] = tmp;
            float t2 = tmp * tmp;
            float td = tmp * dd[ii][jj];
            cpart[jj] += tmp; Apart[jj] += t2; Bpart[jj] += td;
            rc[ii] += tmp;    rA[ii] += t2;    rB[ii] += td;
        }
    }

    float* sb = s_out + (size_t)b * V * V;
#pragma unroll
    for (int ii = 0; ii < 4; ii++) {
        *(float4*)&sb[(i0 + ty * 4 + ii) * V + j0 + tx * 4] =
            make_float4(tm[ii][0], tm[ii][1], tm[ii][2], tm[ii][3]);
    }

#pragma unroll
    for (int jj = 0; jj < 4; jj++) {
        int col = tx * 4 + jj;
        pool[P_CC + col * 17 + ty] = cpart[jj];
        pool[P_AC + col * 17 + ty] = Apart[jj];
        pool[P_BC + col * 17 + ty] = Bpart[jj];
    }
    if (offdiag) {
#pragma unroll
        for (int ii = 0; ii < 4; ii++) {
            int row = ty * 4 + ii;
            pool[P_CR + row * 17 + tx] = rc[ii];
            pool[P_AR + row * 17 + tx] = rA[ii];
            pool[P_BR + row * 17 + tx] = rB[ii];
        }
        // transpose tm into xi region (dead) for the mirror write
#pragma unroll
        for (int jj = 0; jj < 4; jj++) {
            *(float4*)&xi_t[tx * 4 + jj][ty * 4] =
                make_float4(tm[0][jj], tm[1][jj], tm[2][jj], tm[3][jj]);
        }
    }
    __syncthreads();

    if (t < 64) {
        float cs = 0.f, As = 0.f, Bs = 0.f;
#pragma unroll
        for (int u = 0; u < 16; u++) {
            cs += pool[P_CC + t * 17 + u];
            As += pool[P_AC + t * 17 + u];
            Bs += pool[P_BC + t * 17 + u];
        }
        int bc = (b * 4 + it) * V + j0 + t;
        g_pc[bc] = cs; g_pA[bc] = As; g_pB[bc] = Bs;
        if (offdiag) {
            float cr = 0.f, Ar = 0.f, Br = 0.f;
#pragma unroll
            for (int u = 0; u < 16; u++) {
                cr += pool[P_CR + t * 17 + u];
                Ar += pool[P_AR + t * 17 + u];
                Br += pool[P_BR + t * 17 + u];
            }
            int br = (b * 4 + jt) * V + i0 + t;
            g_pc[br] = cr; g_pA[br] = Ar; g_pB[br] = Br;
        }
    }

    if (offdiag) {
        for (int e = t; e < 64 * 16; e += 256) {
            int row = e >> 4;
            int c4 = (e & 15) * 4;
            *(float4*)&sb[(j0 + row) * V + i0 + c4] = *(float4*)&xi_t[row][c4];
        }
    }
}

// ---------------- stage 2 (tf32 tensor, R10 config + hoisted A^2) ----------------
__global__ __launch_bounds__(256) void tf32_gemm_kernel(
    float* __restrict__ s_out, float* __restrict__ gcn, float* __restrict__ out_loss) {
    __shared__ unsigned sA [64][36];
    __shared__ unsigned sA2[64][36];
    __shared__ unsigned sZ1[32][72];
    __shared__ unsigned sZ2[32][72];
    __shared__ float sR[256];

    const int b = blockIdx.y, it = blockIdx.x;
    const int i0 = it * 64;
    const int t = threadIdx.x;
    const int w = t >> 5, l = t & 31;
    const int g = l >> 2, q4 = l & 3;
    const int wr = (w & 3) * 16;
    const int nc0 = (w >> 2) * 32;

    {
        int base = b * 4 * V + t;
        float cs = g_pc[base] + g_pc[base + V] + g_pc[base + 2 * V] + g_pc[base + 3 * V];
        float r = 1.0f / cs;
        sR[t] = r;
        if (it == 0) {
            float A = g_pA[base] + g_pA[base + V] + g_pA[base + 2 * V] + g_pA[base + 3 * V];
            float B = g_pB[base] + g_pB[base + V] + g_pB[base + 2 * V] + g_pB[base + 3 * V];
            ((float*)sZ1)[t] = A * r * r + ALPHA_C * B * r;
        }
    }
    if (it == 0) {
        float* red = (float*)sZ1;
        __syncthreads();
        for (int s = 128; s > 0; s >>= 1) {
            if (t < s) red[t] += red[t + s];
            __syncthreads();
        }
        if (t == 0) g_lossP[b] = red[0];
    }
    __syncthreads();

    float* sb = s_out + (size_t)b * V * V;
    const float* y1g = g_Y + 1 * YSZ + b * V * F;
    const float* y2g = g_Y + 2 * YSZ + b * V * F;

    float acc[4][4];
#pragma unroll
    for (int nt = 0; nt < 4; nt++)
#pragma unroll
        for (int u = 0; u < 4; u++) acc[nt][u] = 0.f;

    for (int ch = 0; ch < 8; ch++) {
        int kc0 = ch * 32;
        for (int e = t; e < 512; e += 256) {
            int i = e >> 3;
            int k4 = (e & 7) * 4;
            float* addr = &sb[(i0 + i) * V + kc0 + k4];
            float4 v = *(const float4*)addr;
            float4 rv = *(const float4*)&sR[kc0 + k4];
            *(float4*)addr = make_float4(v.x * rv.x, v.y * rv.y, v.z * rv.z, v.w * rv.w);
            sA[i][k4 + 0] = cvt_tf32(v.x);
            sA[i][k4 + 1] = cvt_tf32(v.y);
            sA[i][k4 + 2] = cvt_tf32(v.z);
            sA[i][k4 + 3] = cvt_tf32(v.w);
            sA2[i][k4 + 0] = cvt_tf32(v.x * v.x);
            sA2[i][k4 + 1] = cvt_tf32(v.y * v.y);
            sA2[i][k4 + 2] = cvt_tf32(v.z * v.z);
            sA2[i][k4 + 3] = cvt_tf32(v.w * v.w);
        }
        for (int e = t; e < 512; e += 256) {
            int k = e >> 4;
            int c4 = (e & 15) * 4;
            float r = sR[kc0 + k];
            float r2 = r * r;
            float4 v1 = *(const float4*)&y1g[(kc0 + k) * F + c4];
            float4 v2 = *(const float4*)&y2g[(kc0 + k) * F + c4];
            sZ1[k][c4 + 0] = cvt_tf32(v1.x * r);
            sZ1[k][c4 + 1] = cvt_tf32(v1.y * r);
            sZ1[k][c4 + 2] = cvt_tf32(v1.z * r);
            sZ1[k][c4 + 3] = cvt_tf32(v1.w * r);
            sZ2[k][c4 + 0] = cvt_tf32(v2.x * r2);
            sZ2[k][c4 + 1] = cvt_tf32(v2.y * r2);
            sZ2[k][c4 + 2] = cvt_tf32(v2.z * r2);
            sZ2[k][c4 + 3] = cvt_tf32(v2.w * r2);
        }
        __syncthreads();

#pragma unroll
        for (int k8 = 0; k8 < 4; k8++) {
            int kc = k8 * 8;
            int ra = wr + g;
            unsigned a0 = sA[ra][kc + q4];
            unsigned a1 = sA[ra + 8][kc + q4];
            unsigned a2 = sA[ra][kc + 4 + q4];
            unsigned a3 = sA[ra + 8][kc + 4 + q4];
            unsigned q0 = sA2[ra][kc + q4];
            unsigned q1 = sA2[ra + 8][kc + q4];
            unsigned q2 = sA2[ra][kc + 4 + q4];
            unsigned q3 = sA2[ra + 8][kc + 4 + q4];
#pragma unroll
            for (int nt = 0; nt < 4; nt++) {
                int ncol = nc0 + nt * 8 + g;
                unsigned b0 = sZ1[kc + q4][ncol];
                unsigned b1 = sZ1[kc + 4 + q4][ncol];
                mma_tf32(acc[nt], a0, a1, a2, a3, b0, b1);
                unsigned c0 = sZ2[kc + q4][ncol];
                unsigned c1 = sZ2[kc + 4 + q4][ncol];
                mma_tf32(acc[nt], q0, q1, q2, q3, c0, c1);
            }
        }
        __syncthreads();
    }

    const float* y0 = g_Y + b * V * F;
    int r0 = i0 + wr + g, r1 = r0 + 8;
#pragma unroll
    for (int nt = 0; nt < 4; nt++) {
        int col = nc0 + nt * 8 + 2 * q4;
        float2 ya = *(const float2*)&y0[r0 * F + col];
        float2 yb = *(const float2*)&y0[r1 * F + col];
        float2 oa = make_float2(fmaxf(acc[nt][0] + ya.x, 0.f), fmaxf(acc[nt][1] + ya.y, 0.f));
        float2 ob = make_float2(fmaxf(acc[nt][2] + yb.x, 0.f), fmaxf(acc[nt][3] + yb.y, 0.f));
        *(float2*)&gcn[b * V * C + r0 * C + col] = oa;
        *(float2*)&gcn[b * V * C + r1 * C + col] = ob;
    }

    __threadfence();
    __syncthreads();
    if (t == 0) {
        int og = atomicAdd(&g_cntG, 1);
        if (og == NB * 4 - 1) {
            g_cntG = 0;  // reset for next graph replay
            __threadfence();
            float acc2 = 0.f;
#pragma unroll 8
            for (int i = 0; i < NB; i++) acc2 += g_lossP[i];
            *out_loss = acc2;
        }
    }
}

// ---------------- launch ----------------
extern "C" void kernel_launch(void* const* d_in, const int* in_sizes, int n_in,
                              void* d_out, int out_size) {
    const float* x = (const float*)d_in[0];      // (64,256,64)
    const float* a = (const float*)d_in[1];      // (64,)
    const float* theta = (const float*)d_in[2];  // (3,64,64)

    float* out = (float*)d_out;
    float* gcn = out;                                 // NB*V*C
    float* s_out = out + (size_t)NB * V * C;          // NB*V*V
    float* loss = out + (size_t)NB * V * C + (size_t)NB * V * V;  // 1

    mega1_kernel<<<N_PW + N_YG, 256>>>(x, a, theta, s_out);

    dim3 gB(4, NB);
    tf32_gemm_kernel<<<gB, 256>>>(s_out, gcn, loss);
}

// round 16
// speedup vs baseline: 1.0648x; 1.0648x over previous
#include <cuda_runtime.h>
#include <math.h>

#define NB 64
#define V 256
#define F 64
#define C 64
#define ALPHA_C 0.1f
#define YSZ (NB * V * F)

typedef unsigned long long ull;

// ---------------- packed f32x2 helpers (mega1 y-path) ----------------
__device__ __forceinline__ ull pk2(float v) {
    ull r;
    asm("mov.b64 %0, {%1, %1};" : "=l"(r) : "f"(v));
    return r;
}
__device__ __forceinline__ ull fma2(ull a, ull b, ull c) {
    ull r;
    asm("fma.rn.f32x2 %0, %1, %2, %3;" : "=l"(r) : "l"(a), "l"(b), "l"(c));
    return r;
}
__device__ __forceinline__ void upk2(ull v, float& lo, float& hi) {
    asm("mov.b64 {%0, %1}, %2;" : "=f"(lo), "=f"(hi) : "l"(v));
}

// ---------------- tf32 mma helpers ----------------
__device__ __forceinline__ unsigned cvt_tf32(float f) {
    unsigned r;
    asm("cvt.rna.tf32.f32 %0, %1;" : "=r"(r) : "f"(f));
    return r;
}
__device__ __forceinline__ void mma_tf32(float* c,
    unsigned a0, unsigned a1, unsigned a2, unsigned a3,
    unsigned b0, unsigned b1) {
    asm("mma.sync.aligned.m16n8k8.row.col.f32.tf32.tf32.f32 "
        "{%0,%1,%2,%3}, {%4,%5,%6,%7}, {%8,%9}, {%0,%1,%2,%3};"
        : "+f"(c[0]), "+f"(c[1]), "+f"(c[2]), "+f"(c[3])
        : "r"(a0), "r"(a1), "r"(a2), "r"(a3), "r"(b0), "r"(b1));
}

// ---------------- scratch (no allocations allowed) ----------------
__device__ float g_pc[NB * 4 * V];
__device__ float g_pA[NB * 4 * V];
__device__ float g_pB[NB * 4 * V];
__device__ float g_lossP[NB];
__device__ float g_Y[3 * YSZ];   // Y0 = x@(th0-th2), Y1 = x@(-th1), Y2 = x@(2*th2)
__device__ int g_cntG;           // global arrival counter (zero-init; self-resetting)

__constant__ int c_IT[10] = {0, 0, 0, 0, 1, 1, 1, 2, 2, 3};
__constant__ int c_JT[10] = {0, 1, 2, 3, 1, 2, 3, 2, 3, 3};

#define N_PW 640
#define N_YG 768
#define POOL_F 10880
#define A_S 8704
#define NI_O 8768
#define NJ_O 8832
#define NPI_O 8896
#define NPJ_O 9152
#define P_CC 4352
#define P_AC (4352 + 1088)
#define P_BC (4352 + 2176)
#define P_CR (4352 + 3264)
#define P_AR (4352 + 4352)
#define P_BR (4352 + 5440)

// ---------------- mega kernel 1: pairwise (idx<640) + y_gemm (idx>=640) ----------------
__global__ __launch_bounds__(256) void mega1_kernel(
    const float* __restrict__ x, const float* __restrict__ a,
    const float* __restrict__ theta, float* __restrict__ s_out) {
    __shared__ __align__(16) float pool[POOL_F];

    const int t = threadIdx.x;
    const int tx = t & 15, ty = t >> 4;

    if (blockIdx.x >= N_PW) {
        // ================= y_gemm part =================
        int idx = blockIdx.x - N_PW;
        const int it = idx & 3;
        const int m = (idx >> 2) % 3;
        const int b = idx / 12;
        const int i0 = it * 64;
        float (*sW)[64] = (float(*)[64])pool;
        float (*sX)[68] = (float(*)[68])(pool + 4096);
        const float* xb = x + b * V * F;

        for (int q = t; q < 64 * 16; q += 256) {
            int f = q >> 4;
            int c4 = (q & 15) * 4;
            float4 v;
            if (m == 0) {
                float4 t0 = *(const float4*)&theta[(0 * F + f) * C + c4];
                float4 t2 = *(const float4*)&theta[(2 * F + f) * C + c4];
                v = make_float4(t0.x - t2.x, t0.y - t2.y, t0.z - t2.z, t0.w - t2.w);
            } else if (m == 1) {
                float4 t1 = *(const float4*)&theta[(1 * F + f) * C + c4];
                v = make_float4(-t1.x, -t1.y, -t1.z, -t1.w);
            } else {
                float4 t2 = *(const float4*)&theta[(2 * F + f) * C + c4];
                v = make_float4(2.f * t2.x, 2.f * t2.y, 2.f * t2.z, 2.f * t2.w);
            }
            *(float4*)&sW[f][c4] = v;
        }
        for (int q = t; q < 64 * 16; q += 256) {
            int i = q >> 4;
            int f4 = (q & 15) * 4;
            float4 v = *(const float4*)&xb[(i0 + i) * F + f4];
            sX[f4 + 0][i] = v.x;
            sX[f4 + 1][i] = v.y;
            sX[f4 + 2][i] = v.z;
            sX[f4 + 3][i] = v.w;
        }
        __syncthreads();

        ull acc2[4][2];
#pragma unroll
        for (int ii = 0; ii < 4; ii++)
#pragma unroll
            for (int p = 0; p < 2; p++) acc2[ii][p] = 0ULL;

#pragma unroll 4
        for (int k = 0; k < 64; k++) {
            float4 xa = *(const float4*)&sX[k][ty * 4];
            ulonglong2 wp = *(const ulonglong2*)&sW[k][tx * 4];
            float xv[4] = {xa.x, xa.y, xa.z, xa.w};
#pragma unroll
            for (int ii = 0; ii < 4; ii++) {
                ull xv2 = pk2(xv[ii]);
                acc2[ii][0] = fma2(xv2, wp.x, acc2[ii][0]);
                acc2[ii][1] = fma2(xv2, wp.y, acc2[ii][1]);
            }
        }

        float* y = g_Y + m * YSZ + b * V * F;
#pragma unroll
        for (int ii = 0; ii < 4; ii++) {
            int row = i0 + ty * 4 + ii;
            float4 o;
            upk2(acc2[ii][0], o.x, o.y);
            upk2(acc2[ii][1], o.z, o.w);
            *(float4*)&y[row * F + tx * 4] = o;
        }
        return;
    }

    // ================= pairwise part =================
    const int b = blockIdx.x / 10;
    const int tile = blockIdx.x % 10;
    const int it = c_IT[tile], jt = c_JT[tile];
    const int i0 = it * 64, j0 = jt * 64;
    const bool offdiag = (it != jt);
    const float* xb = x + b * V * F;

    float (*xi_t)[68] = (float(*)[68])pool;           // [f][i]
    float (*xj_t)[68] = (float(*)[68])(pool + 4352);  // [f][j]
    float* a_s = pool + A_S;

    for (int e = t; e < 64 * F; e += 256) {
        int row = e >> 6;
        int f = e & 63;
        xi_t[f][row] = xb[(i0 + row) * F + f];
        xj_t[f][row] = xb[(j0 + row) * F + f];
    }
    if (t < F) a_s[t] = a[t];
    __syncthreads();

    // ---- 1. score-only scalar loop ----
    float sc[4][4];
#pragma unroll
    for (int ii = 0; ii < 4; ii++)
#pragma unroll
        for (int jj = 0; jj < 4; jj++) sc[ii][jj] = 0.f;

#pragma unroll 4
    for (int f = 0; f < F; f++) {
        float4 xi4 = *(const float4*)&xi_t[f][ty * 4];
        float4 xj4 = *(const float4*)&xj_t[f][tx * 4];
        float xiv[4] = {xi4.x, xi4.y, xi4.z, xi4.w};
        float xjv[4] = {xj4.x, xj4.y, xj4.z, xj4.w};
        float af = a_s[f];
#pragma unroll
        for (int ii = 0; ii < 4; ii++)
#pragma unroll
            for (int jj = 0; jj < 4; jj++) {
                float d = xiv[ii] - xjv[jj];
                sc[ii][jj] = fmaf(fabsf(d), af, sc[ii][jj]);
            }
    }

    // ---- 2. row/col squared norms (partials) ----
    {
        int row = t & 63, qtr = t >> 6;
        float npi = 0.f, npj = 0.f;
#pragma unroll
        for (int u = 0; u < 16; u++) {
            float vi = xi_t[qtr * 16 + u][row];
            float vj = xj_t[qtr * 16 + u][row];
            npi = fmaf(vi, vi, npi);
            npj = fmaf(vj, vj, npj);
        }
        pool[NPI_O + qtr * 64 + row] = npi;
        pool[NPJ_O + qtr * 64 + row] = npj;
    }

    // ---- 3. Gram tile via tf32 mma (raw fp32 bits) ----
    const int w = t >> 5, l = t & 31;
    const int g2 = l >> 2, q4 = l & 3;
    const int wr = (w & 3) * 16;
    const int nc = (w >> 2) * 32;

    float gacc[4][4];
#pragma unroll
    for (int nt = 0; nt < 4; nt++)
#pragma unroll
        for (int u = 0; u < 4; u++) gacc[nt][u] = 0.f;

#pragma unroll
    for (int kk = 0; kk < 8; kk++) {
        int kc = kk * 8;
        unsigned a0 = __float_as_uint(xi_t[kc + q4][wr + g2]);
        unsigned a1 = __float_as_uint(xi_t[kc + q4][wr + g2 + 8]);
        unsigned a2 = __float_as_uint(xi_t[kc + 4 + q4][wr + g2]);
        unsigned a3 = __float_as_uint(xi_t[kc + 4 + q4][wr + g2 + 8]);
#pragma unroll
        for (int nt = 0; nt < 4; nt++) {
            int ncol = nc + nt * 8 + g2;
            unsigned b0 = __float_as_uint(xj_t[kc + q4][ncol]);
            unsigned b1 = __float_as_uint(xj_t[kc + 4 + q4][ncol]);
            mma_tf32(gacc[nt], a0, a1, a2, a3, b0, b1);
        }
    }
    __syncthreads();

    // ---- 4. reduce norms ----
    if (t < 64) {
        pool[NI_O + t] = pool[NPI_O + t] + pool[NPI_O + 64 + t] +
                         pool[NPI_O + 128 + t] + pool[NPI_O + 192 + t];
        pool[NJ_O + t] = pool[NPJ_O + t] + pool[NPJ_O + 64 + t] +
                         pool[NPJ_O + 128 + t] + pool[NPJ_O + 192 + t];
    }
    __syncthreads();

    // ---- 5. d2 tile (overlays dead xj region); exact 0 on diagonal ----
    float (*d2t)[68] = (float(*)[68])(pool + 4352);
#pragma unroll
    for (int nt = 0; nt < 4; nt++) {
        int col = nc + nt * 8 + 2 * q4;
        int r0 = wr + g2, r1 = r0 + 8;
        float ni0 = pool[NI_O + r0], ni1 = pool[NI_O + r1];
        float nj0 = pool[NJ_O + col], nj1 = pool[NJ_O + col + 1];
        float v00 = ni0 + nj0 - 2.f * gacc[nt][0];
        float v01 = ni0 + nj1 - 2.f * gacc[nt][1];
        float v10 = ni1 + nj0 - 2.f * gacc[nt][2];
        float v11 = ni1 + nj1 - 2.f * gacc[nt][3];
        if (!offdiag) {
            if (r0 == col) v00 = 0.f;
            if (r0 == col + 1) v01 = 0.f;
            if (r1 == col) v10 = 0.f;
            if (r1 == col + 1) v11 = 0.f;
        }
        *(float2*)&d2t[r0][col] = make_float2(v00, v01);
        *(float2*)&d2t[r1][col] = make_float2(v10, v11);
    }
    __syncthreads();

    // ---- 6. cache dd in registers ----
    float dd[4][4];
#pragma unroll
    for (int ii = 0; ii < 4; ii++)
        *(float4*)dd[ii] = *(const float4*)&d2t[ty * 4 + ii][tx * 4];
    __syncthreads();

    // ---- 7. stats epilogue ----
    float tm[4][4];
    float cpart[4] = {0.f, 0.f, 0.f, 0.f};
    float Apart[4] = {0.f, 0.f, 0.f, 0.f};
    float Bpart[4] = {0.f, 0.f, 0.f, 0.f};
    float rc[4] = {0.f, 0.f, 0.f, 0.f};
    float rA[4] = {0.f, 0.f, 0.f, 0.f};
    float rB[4] = {0.f, 0.f, 0.f, 0.f};

#pragma unroll
    for (int ii = 0; ii < 4; ii++) {
#pragma unroll
        for (int jj = 0; jj < 4; jj++) {
            float tmp = __expf(-fmaxf(sc[ii][jj], 0.f));
            tm[ii][jj] = tmp;
            float t2 = tmp * tmp;
            float td = tmp * dd[ii][jj];
            cpart[jj] += tmp; Apart[jj] += t2; Bpart[jj] += td;
            rc[ii] += tmp;    rA[ii] += t2;    rB[ii] += td;
        }
    }

    float* sb = s_out + (size_t)b * V * V;
#pragma unroll
    for (int ii = 0; ii < 4; ii++) {
        *(float4*)&sb[(i0 + ty * 4 + ii) * V + j0 + tx * 4] =
            make_float4(tm[ii][0], tm[ii][1], tm[ii][2], tm[ii][3]);
    }

#pragma unroll
    for (int jj = 0; jj < 4; jj++) {
        int col = tx * 4 + jj;
        pool[P_CC + col * 17 + ty] = cpart[jj];
        pool[P_AC + col * 17 + ty] = Apart[jj];
        pool[P_BC + col * 17 + ty] = Bpart[jj];
    }
    if (offdiag) {
#pragma unroll
        for (int ii = 0; ii < 4; ii++) {
            int row = ty * 4 + ii;
            pool[P_CR + row * 17 + tx] = rc[ii];
            pool[P_AR + row * 17 + tx] = rA[ii];
            pool[P_BR + row * 17 + tx] = rB[ii];
        }
#pragma unroll
        for (int jj = 0; jj < 4; jj++) {
            *(float4*)&xi_t[tx * 4 + jj][ty * 4] =
                make_float4(tm[0][jj], tm[1][jj], tm[2][jj], tm[3][jj]);
        }
    }
    __syncthreads();

    if (t < 64) {
        float cs = 0.f, As = 0.f, Bs = 0.f;
#pragma unroll
        for (int u = 0; u < 16; u++) {
            cs += pool[P_CC + t * 17 + u];
            As += pool[P_AC + t * 17 + u];
            Bs += pool[P_BC + t * 17 + u];
        }
        int bc = (b * 4 + it) * V + j0 + t;
        g_pc[bc] = cs; g_pA[bc] = As; g_pB[bc] = Bs;
        if (offdiag) {
            float cr = 0.f, Ar = 0.f, Br = 0.f;
#pragma unroll
            for (int u = 0; u < 16; u++) {
                cr += pool[P_CR + t * 17 + u];
                Ar += pool[P_AR + t * 17 + u];
                Br += pool[P_BR + t * 17 + u];
            }
            int br = (b * 4 + jt) * V + i0 + t;
            g_pc[br] = cr; g_pA[br] = Ar; g_pB[br] = Br;
        }
    }

    if (offdiag) {
        for (int e = t; e < 64 * 16; e += 256) {
            int row = e >> 4;
            int c4 = (e & 15) * 4;
            *(float4*)&sb[(j0 + row) * V + i0 + c4] = *(float4*)&xi_t[row][c4];
        }
    }
}

// ---------------- stage 2: tf32 GEMM with register-prefetch double buffering ----------------
// gcn = relu(Y0 + tmp@Z1 + tmp^2@Z2). Grid (4 it, 64 b), 256 thr.
// Each thread prefetches chunk ch+1's 6 float4s during chunk ch's MMA phase.
__global__ __launch_bounds__(256) void tf32_gemm_kernel(
    float* __restrict__ s_out, float* __restrict__ gcn, float* __restrict__ out_loss) {
    __shared__ unsigned sA [64][36];
    __shared__ unsigned sA2[64][36];
    __shared__ unsigned sZ1[32][72];
    __shared__ unsigned sZ2[32][72];
    __shared__ float sR[256];

    const int b = blockIdx.y, it = blockIdx.x;
    const int i0 = it * 64;
    const int t = threadIdx.x;
    const int w = t >> 5, l = t & 31;
    const int g = l >> 2, q4 = l & 3;
    const int wr = (w & 3) * 16;
    const int nc0 = (w >> 2) * 32;

    // staging indices (fixed per thread)
    const int iA = t >> 3;                 // rows iA and iA+32
    const int kA = (t & 7) * 4;            // 4 k-cols
    const int kZ = t >> 4;                 // k rows kZ and kZ+16
    const int cZ = (t & 15) * 4;           // 4 c-cols

    float* sb = s_out + (size_t)b * V * V;
    const float* y1g = g_Y + 1 * YSZ + b * V * F;
    const float* y2g = g_Y + 2 * YSZ + b * V * F;

    // initial prefetch (chunk 0) — issued before the preamble to overlap its LDGs
    float4 pA0 = *(const float4*)&sb[(i0 + iA) * V + kA];
    float4 pA1 = *(const float4*)&sb[(i0 + iA + 32) * V + kA];
    float4 pY10 = *(const float4*)&y1g[kZ * F + cZ];
    float4 pY11 = *(const float4*)&y1g[(kZ + 16) * F + cZ];
    float4 pY20 = *(const float4*)&y2g[kZ * F + cZ];
    float4 pY21 = *(const float4*)&y2g[(kZ + 16) * F + cZ];

    // preamble: r for all 256 cols, loss partial on it==0
    {
        int base = b * 4 * V + t;
        float cs = g_pc[base] + g_pc[base + V] + g_pc[base + 2 * V] + g_pc[base + 3 * V];
        float r = 1.0f / cs;
        sR[t] = r;
        if (it == 0) {
            float A = g_pA[base] + g_pA[base + V] + g_pA[base + 2 * V] + g_pA[base + 3 * V];
            float B = g_pB[base] + g_pB[base + V] + g_pB[base + 2 * V] + g_pB[base + 3 * V];
            ((float*)sZ1)[t] = A * r * r + ALPHA_C * B * r;
        }
    }
    if (it == 0) {
        float* red = (float*)sZ1;
        __syncthreads();
        for (int s = 128; s > 0; s >>= 1) {
            if (t < s) red[t] += red[t + s];
            __syncthreads();
        }
        if (t == 0) g_lossP[b] = red[0];
    }
    __syncthreads();

    float acc[4][4];
#pragma unroll
    for (int nt = 0; nt < 4; nt++)
#pragma unroll
        for (int u = 0; u < 4; u++) acc[nt][u] = 0.f;

    for (int ch = 0; ch < 8; ch++) {
        int kc0 = ch * 32;

        // ---- store phase: consume prefetched registers ----
        {
            float4 rvA = *(const float4*)&sR[kc0 + kA];
            float* ad0 = &sb[(i0 + iA) * V + kc0 + kA];
            *(float4*)ad0 = make_float4(pA0.x * rvA.x, pA0.y * rvA.y,
                                        pA0.z * rvA.z, pA0.w * rvA.w);
            sA[iA][kA + 0] = cvt_tf32(pA0.x);
            sA[iA][kA + 1] = cvt_tf32(pA0.y);
            sA[iA][kA + 2] = cvt_tf32(pA0.z);
            sA[iA][kA + 3] = cvt_tf32(pA0.w);
            sA2[iA][kA + 0] = cvt_tf32(pA0.x * pA0.x);
            sA2[iA][kA + 1] = cvt_tf32(pA0.y * pA0.y);
            sA2[iA][kA + 2] = cvt_tf32(pA0.z * pA0.z);
            sA2[iA][kA + 3] = cvt_tf32(pA0.w * pA0.w);

            float* ad1 = &sb[(i0 + iA + 32) * V + kc0 + kA];
            *(float4*)ad1 = make_float4(pA1.x * rvA.x, pA1.y * rvA.y,
                                        pA1.z * rvA.z, pA1.w * rvA.w);
            sA[iA + 32][kA + 0] = cvt_tf32(pA1.x);
            sA[iA + 32][kA + 1] = cvt_tf32(pA1.y);
            sA[iA + 32][kA + 2] = cvt_tf32(pA1.z);
            sA[iA + 32][kA + 3] = cvt_tf32(pA1.w);
            sA2[iA + 32][kA + 0] = cvt_tf32(pA1.x * pA1.x);
            sA2[iA + 32][kA + 1] = cvt_tf32(pA1.y * pA1.y);
            sA2[iA + 32][kA + 2] = cvt_tf32(pA1.z * pA1.z);
            sA2[iA + 32][kA + 3] = cvt_tf32(pA1.w * pA1.w);

            float r0 = sR[kc0 + kZ], r0s = r0 * r0;
            sZ1[kZ][cZ + 0] = cvt_tf32(pY10.x * r0);
            sZ1[kZ][cZ + 1] = cvt_tf32(pY10.y * r0);
            sZ1[kZ][cZ + 2] = cvt_tf32(pY10.z * r0);
            sZ1[kZ][cZ + 3] = cvt_tf32(pY10.w * r0);
            sZ2[kZ][cZ + 0] = cvt_tf32(pY20.x * r0s);
            sZ2[kZ][cZ + 1] = cvt_tf32(pY20.y * r0s);
            sZ2[kZ][cZ + 2] = cvt_tf32(pY20.z * r0s);
            sZ2[kZ][cZ + 3] = cvt_tf32(pY20.w * r0s);

            float r1 = sR[kc0 + kZ + 16], r1s = r1 * r1;
            sZ1[kZ + 16][cZ + 0] = cvt_tf32(pY11.x * r1);
            sZ1[kZ + 16][cZ + 1] = cvt_tf32(pY11.y * r1);
            sZ1[kZ + 16][cZ + 2] = cvt_tf32(pY11.z * r1);
            sZ1[kZ + 16][cZ + 3] = cvt_tf32(pY11.w * r1);
            sZ2[kZ + 16][cZ + 0] = cvt_tf32(pY21.x * r1s);
            sZ2[kZ + 16][cZ + 1] = cvt_tf32(pY21.y * r1s);
            sZ2[kZ + 16][cZ + 2] = cvt_tf32(pY21.z * r1s);
            sZ2[kZ + 16][cZ + 3] = cvt_tf32(pY21.w * r1s);
        }
        __syncthreads();

        // ---- prefetch next chunk (overlaps the MMA phase below) ----
        if (ch < 7) {
            int kn = kc0 + 32;
            pA0 = *(const float4*)&sb[(i0 + iA) * V + kn + kA];
            pA1 = *(const float4*)&sb[(i0 + iA + 32) * V + kn + kA];
            pY10 = *(const float4*)&y1g[(kn + kZ) * F + cZ];
            pY11 = *(const float4*)&y1g[(kn + kZ + 16) * F + cZ];
            pY20 = *(const float4*)&y2g[(kn + kZ) * F + cZ];
            pY21 = *(const float4*)&y2g[(kn + kZ + 16) * F + cZ];
        }

        // ---- MMA phase ----
#pragma unroll
        for (int k8 = 0; k8 < 4; k8++) {
            int kc = k8 * 8;
            int ra = wr + g;
            unsigned a0 = sA[ra][kc + q4];
            unsigned a1 = sA[ra + 8][kc + q4];
            unsigned a2 = sA[ra][kc + 4 + q4];
            unsigned a3 = sA[ra + 8][kc + 4 + q4];
            unsigned q0 = sA2[ra][kc + q4];
            unsigned q1 = sA2[ra + 8][kc + q4];
            unsigned q2 = sA2[ra][kc + 4 + q4];
            unsigned q3 = sA2[ra + 8][kc + 4 + q4];
#pragma unroll
            for (int nt = 0; nt < 4; nt++) {
                int ncol = nc0 + nt * 8 + g;
                unsigned b0 = sZ1[kc + q4][ncol];
                unsigned b1 = sZ1[kc + 4 + q4][ncol];
                mma_tf32(acc[nt], a0, a1, a2, a3, b0, b1);
                unsigned c0 = sZ2[kc + q4][ncol];
                unsigned c1 = sZ2[kc + 4 + q4][ncol];
                mma_tf32(acc[nt], q0, q1, q2, q3, c0, c1);
            }
        }
        __syncthreads();
    }

    // epilogue: gcn = relu(Y0 + acc)
    const float* y0 = g_Y + b * V * F;
    int r0 = i0 + wr + g, r1 = r0 + 8;
#pragma unroll
    for (int nt = 0; nt < 4; nt++) {
        int col = nc0 + nt * 8 + 2 * q4;
        float2 ya = *(const float2*)&y0[r0 * F + col];
        float2 yb = *(const float2*)&y0[r1 * F + col];
        float2 oa = make_float2(fmaxf(acc[nt][0] + ya.x, 0.f), fmaxf(acc[nt][1] + ya.y, 0.f));
        float2 ob = make_float2(fmaxf(acc[nt][2] + yb.x, 0.f), fmaxf(acc[nt][3] + yb.y, 0.f));
        *(float2*)&gcn[b * V * C + r0 * C + col] = oa;
        *(float2*)&gcn[b * V * C + r1 * C + col] = ob;
    }

    // loss finisher
    __threadfence();
    __syncthreads();
    if (t == 0) {
        int og = atomicAdd(&g_cntG, 1);
        if (og == NB * 4 - 1) {
            g_cntG = 0;  // reset for next graph replay
            __threadfence();
            float acc2 = 0.f;
#pragma unroll 8
            for (int i = 0; i < NB; i++) acc2 += g_lossP[i];
            *out_loss = acc2;
        }
    }
}

// ---------------- launch ----------------
extern "C" void kernel_launch(void* const* d_in, const int* in_sizes, int n_in,
                              void* d_out, int out_size) {
    const float* x = (const float*)d_in[0];      // (64,256,64)
    const float* a = (const float*)d_in[1];      // (64,)
    const float* theta = (const float*)d_in[2];  // (3,64,64)

    float* out = (float*)d_out;
    float* gcn = out;                                 // NB*V*C
    float* s_out = out + (size_t)NB * V * C;          // NB*V*V
    float* loss = out + (size_t)NB * V * C + (size_t)NB * V * V;  // 1

    mega1_kernel<<<N_PW + N_YG, 256>>>(x, a, theta, s_out);

    dim3 gB(4, NB);
    tf32_gemm_kernel<<<gB, 256>>>(s_out, gcn, loss);
}